// round 4
// baseline (speedup 1.0000x reference)
#include <cuda_runtime.h>
#include <cuda_bf16.h>
#include <math.h>

#define N_NODES 100000
#define N_EDGES 3200000
#define F_IN    512
#define HID     16
#define NCLS    40

// ---------------------------------------------------------------------------
// Scratch (device globals — no allocation allowed). Every buffer is fully
// rewritten each launch -> deterministic up to atomic fp ordering.
// ---------------------------------------------------------------------------
__device__ __align__(128) float g_deg[N_NODES];
__device__ __align__(128) float g_dis[N_NODES];
__device__ __align__(128) float g_g1 [N_NODES * HID];   // h1 * dis (gather source, layer 1)
__device__ __align__(128) float g_ac1[N_NODES * HID];   // accumulator, layer 1
__device__ __align__(128) float g_g2 [N_NODES * HID];   // relu(...)*dis (gather source, layer 2)
__device__ __align__(128) float g_ac2[N_NODES * HID];   // accumulator, layer 2

// Vector reduction: 1 LTS op for 4 floats (sm_90+).
__device__ __forceinline__ void red_add_v4(float* addr, float4 v) {
    asm volatile("red.global.add.v4.f32 [%0], {%1, %2, %3, %4};"
                 :: "l"(addr), "f"(v.x), "f"(v.y), "f"(v.z), "f"(v.w)
                 : "memory");
}

// ---------------------------------------------------------------------------
// K1: deg = 1.0 (self loop)
// ---------------------------------------------------------------------------
__global__ void k_init_deg() {
    int i = blockIdx.x * blockDim.x + threadIdx.x;
    if (i < N_NODES) g_deg[i] = 1.0f;
}

// ---------------------------------------------------------------------------
// K2: degree count at dst (edge_index is int32: row0 = src, row1 = dst)
//     2 edges per thread.
// ---------------------------------------------------------------------------
__global__ __launch_bounds__(256) void k_count_deg(const int* __restrict__ ei) {
    int base = (blockIdx.x * blockDim.x + threadIdx.x) * 2;
    if (base + 1 < N_EDGES) {
        int d0 = __ldg(&ei[N_EDGES + base]);
        int d1 = __ldg(&ei[N_EDGES + base + 1]);
        atomicAdd(&g_deg[d0], 1.0f);
        atomicAdd(&g_deg[d1], 1.0f);
    } else if (base < N_EDGES) {
        int d0 = __ldg(&ei[N_EDGES + base]);
        atomicAdd(&g_deg[d0], 1.0f);
    }
}

// ---------------------------------------------------------------------------
// K3: g1 = (x @ W1) * deg^-1/2  (one warp per row; W1 transposed in smem)
//     also stores dis and initializes acc1 = g1 (the self-loop term).
// ---------------------------------------------------------------------------
__global__ __launch_bounds__(256) void k_gemm1(const float* __restrict__ x,
                                               const float* __restrict__ W1) {
    __shared__ __align__(16) float Wt[HID * F_IN];   // 16 x 512 = 32 KB, transposed

    // cooperative transpose-load of W1 [512,16] -> Wt [16][512]
    for (int idx = threadIdx.x; idx < F_IN * HID; idx += 256) {
        int c = idx >> 4;          // 0..511
        int j = idx & 15;          // 0..15
        Wt[j * F_IN + c] = W1[idx];
    }
    __syncthreads();

    int warp = threadIdx.x >> 5;
    int lane = threadIdx.x & 31;
    int row  = blockIdx.x * 8 + warp;
    if (row >= N_NODES) return;

    const float4* xr = (const float4*)(x + (size_t)row * F_IN);

    float acc[HID];
#pragma unroll
    for (int j = 0; j < HID; j++) acc[j] = 0.0f;

#pragma unroll
    for (int k = 0; k < 4; k++) {                       // 128 float4 per row / 32 lanes
        float4 xv = xr[lane + 32 * k];
#pragma unroll
        for (int j = 0; j < HID; j++) {
            float4 w = ((const float4*)(Wt + j * F_IN))[lane + 32 * k];
            acc[j] += xv.x * w.x + xv.y * w.y + xv.z * w.z + xv.w * w.w;
        }
    }

    // full warp reduction
#pragma unroll
    for (int j = 0; j < HID; j++) {
#pragma unroll
        for (int off = 16; off > 0; off >>= 1)
            acc[j] += __shfl_xor_sync(0xffffffffu, acc[j], off);
    }

    if (lane == 0) {
        float dv = rsqrtf(g_deg[row]);
        g_dis[row] = dv;
        float4* pg = (float4*)(g_g1  + (size_t)row * HID);
        float4* pa = (float4*)(g_ac1 + (size_t)row * HID);
#pragma unroll
        for (int k = 0; k < 4; k++) {
            float4 v = make_float4(acc[4*k+0]*dv, acc[4*k+1]*dv,
                                   acc[4*k+2]*dv, acc[4*k+3]*dv);
            pg[k] = v;
            pa[k] = v;
        }
    }
}

// ---------------------------------------------------------------------------
// K4/K6: edge propagation  acc[dst] += g[src]   (16 floats = 4 x red.v4)
// ---------------------------------------------------------------------------
template <int LAYER>
__global__ __launch_bounds__(256) void k_edges(const int* __restrict__ ei) {
    const float* __restrict__ gsrc = (LAYER == 1 ? g_g1 : g_g2);
    float*       __restrict__ gacc = (LAYER == 1 ? g_ac1 : g_ac2);
    int e = blockIdx.x * blockDim.x + threadIdx.x;
    if (e >= N_EDGES) return;
    int s = __ldg(&ei[e]);
    int d = __ldg(&ei[N_EDGES + e]);
    const float4* gs = (const float4*)(gsrc + (size_t)s * HID);
    float*        ad = gacc + (size_t)d * HID;
    float4 v0 = __ldg(&gs[0]);
    float4 v1 = __ldg(&gs[1]);
    float4 v2 = __ldg(&gs[2]);
    float4 v3 = __ldg(&gs[3]);
    red_add_v4(ad + 0,  v0);
    red_add_v4(ad + 4,  v1);
    red_add_v4(ad + 8,  v2);
    red_add_v4(ad + 12, v3);
}

// ---------------------------------------------------------------------------
// K5: finalize layer 1:  t = relu(acc1*dis + b1);  g2 = t*dis;  acc2 = g2
// ---------------------------------------------------------------------------
__global__ __launch_bounds__(256) void k_finalize1(const float* __restrict__ b1) {
    int i = blockIdx.x * blockDim.x + threadIdx.x;
    if (i >= N_NODES) return;
    float dv = g_dis[i];
    const float4* pa = (const float4*)(g_ac1 + (size_t)i * HID);
    float4* pg = (float4*)(g_g2  + (size_t)i * HID);
    float4* pc = (float4*)(g_ac2 + (size_t)i * HID);
#pragma unroll
    for (int k = 0; k < 4; k++) {
        float4 a = pa[k];
        float c0 = __ldg(&b1[4*k+0]), c1 = __ldg(&b1[4*k+1]);
        float c2 = __ldg(&b1[4*k+2]), c3 = __ldg(&b1[4*k+3]);
        float4 t;
        t.x = fmaxf(a.x * dv + c0, 0.0f) * dv;
        t.y = fmaxf(a.y * dv + c1, 0.0f) * dv;
        t.z = fmaxf(a.z * dv + c2, 0.0f) * dv;
        t.w = fmaxf(a.w * dv + c3, 0.0f) * dv;
        pg[k] = t;
        pc[k] = t;
    }
}

// ---------------------------------------------------------------------------
// K7: epilogue: p = acc2*dis; o = p @ W2 + b2; log_softmax; write out.
//     (W2 hoisted after propagation: A(rW2) = (Ar)W2 by linearity)
// ---------------------------------------------------------------------------
__global__ __launch_bounds__(256) void k_output(const float* __restrict__ W2,
                                                const float* __restrict__ b2,
                                                float* __restrict__ out) {
    __shared__ float W2s[HID * NCLS];
    __shared__ float b2s[NCLS];
    for (int idx = threadIdx.x; idx < HID * NCLS; idx += 256) W2s[idx] = W2[idx];
    for (int idx = threadIdx.x; idx < NCLS; idx += 256) b2s[idx] = b2[idx];
    __syncthreads();

    int i = blockIdx.x * blockDim.x + threadIdx.x;
    if (i >= N_NODES) return;

    float dv = g_dis[i];
    float o[NCLS];
#pragma unroll
    for (int j = 0; j < NCLS; j++) o[j] = b2s[j];

    const float4* pa = (const float4*)(g_ac2 + (size_t)i * HID);
#pragma unroll
    for (int k = 0; k < 4; k++) {
        float4 a = pa[k];
        float p0 = a.x * dv, p1 = a.y * dv, p2 = a.z * dv, p3 = a.w * dv;
        int c = 4 * k;
#pragma unroll
        for (int j = 0; j < NCLS; j++) {
            o[j] += p0 * W2s[(c+0)*NCLS + j] + p1 * W2s[(c+1)*NCLS + j]
                  + p2 * W2s[(c+2)*NCLS + j] + p3 * W2s[(c+3)*NCLS + j];
        }
    }

    float m = o[0];
#pragma unroll
    for (int j = 1; j < NCLS; j++) m = fmaxf(m, o[j]);
    float ssum = 0.0f;
#pragma unroll
    for (int j = 0; j < NCLS; j++) ssum += expf(o[j] - m);
    float ls = m + logf(ssum);

    float* op = out + (size_t)i * NCLS;
#pragma unroll
    for (int j = 0; j < NCLS; j++) op[j] = o[j] - ls;
}

// ---------------------------------------------------------------------------
extern "C" void kernel_launch(void* const* d_in, const int* in_sizes, int n_in,
                              void* d_out, int out_size) {
    (void)in_sizes; (void)n_in; (void)out_size;
    const float* x   = (const float*)d_in[0];
    const int*   ei  = (const int*)d_in[1];     // int32 (JAX x64 disabled)
    const float* W1  = (const float*)d_in[2];
    const float* b1  = (const float*)d_in[3];
    const float* W2  = (const float*)d_in[4];
    const float* b2  = (const float*)d_in[5];
    float*       out = (float*)d_out;

    const int TB = 256;
    k_init_deg  <<<(N_NODES + TB - 1) / TB, TB>>>();
    k_count_deg <<<(N_EDGES / 2 + TB - 1) / TB, TB>>>(ei);
    k_gemm1     <<<(N_NODES + 7) / 8, 256>>>(x, W1);
    k_edges<1>  <<<(N_EDGES + TB - 1) / TB, TB>>>(ei);
    k_finalize1 <<<(N_NODES + TB - 1) / TB, TB>>>(b1);
    k_edges<2>  <<<(N_EDGES + TB - 1) / TB, TB>>>(ei);
    k_output    <<<(N_NODES + TB - 1) / TB, TB>>>(W2, b2, out);
}

// round 7
// speedup vs baseline: 1.8358x; 1.8358x over previous
#include <cuda_runtime.h>
#include <cuda_bf16.h>
#include <math.h>

#define N_NODES 100000
#define N_EDGES 3200000
#define F_IN    512
#define HID     16
#define NCLS    40

// ---------------------------------------------------------------------------
// Scratch (device globals — no allocation allowed).
// ---------------------------------------------------------------------------
__device__ __align__(128) float g_deg[N_NODES];
__device__ __align__(128) float g_dis[N_NODES];
__device__ __align__(128) float g_g1 [N_NODES * HID];
__device__ __align__(128) float g_ac1[N_NODES * HID];
__device__ __align__(128) float g_g2 [N_NODES * HID];
__device__ __align__(128) float g_ac2[N_NODES * HID];

__device__ __forceinline__ void red_add_v4(float* addr, float4 v) {
    asm volatile("red.global.add.v4.f32 [%0], {%1, %2, %3, %4};"
                 :: "l"(addr), "f"(v.x), "f"(v.y), "f"(v.z), "f"(v.w)
                 : "memory");
}

// ---------------------------------------------------------------------------
// K1: deg = 1.0 (self loop)
// ---------------------------------------------------------------------------
__global__ void k_init_deg() {
    int i = blockIdx.x * blockDim.x + threadIdx.x;
    if (i < N_NODES) g_deg[i] = 1.0f;
}

// ---------------------------------------------------------------------------
// K2: degree count at dst. 2 edges per thread.
// ---------------------------------------------------------------------------
__global__ __launch_bounds__(256) void k_count_deg(const int* __restrict__ ei) {
    int base = (blockIdx.x * blockDim.x + threadIdx.x) * 2;
    if (base + 1 < N_EDGES) {
        int d0 = __ldg(&ei[N_EDGES + base]);
        int d1 = __ldg(&ei[N_EDGES + base + 1]);
        atomicAdd(&g_deg[d0], 1.0f);
        atomicAdd(&g_deg[d1], 1.0f);
    } else if (base < N_EDGES) {
        int d0 = __ldg(&ei[N_EDGES + base]);
        atomicAdd(&g_deg[d0], 1.0f);
    }
}

// ---------------------------------------------------------------------------
// K3: g1 = (x @ W1) * deg^-1/2 ; acc1 = g1.
// 4 rows per warp per iteration (each Wt read feeds 4 rows), grid-stride
// over row-groups so the smem transpose amortizes over ~100 rows per block.
// ---------------------------------------------------------------------------
#define G1_BLOCKS 888           // ~6 blocks/SM at 32KB smem
#define RPW 4                   // rows per warp per group

__global__ __launch_bounds__(256) void k_gemm1(const float* __restrict__ x,
                                               const float* __restrict__ W1) {
    __shared__ __align__(16) float Wt[HID * F_IN];   // 32 KB, W1 transposed

    for (int idx = threadIdx.x; idx < F_IN * HID; idx += 256) {
        int c = idx >> 4;
        int j = idx & 15;
        Wt[j * F_IN + c] = W1[idx];
    }
    __syncthreads();

    const int warp = threadIdx.x >> 5;
    const int lane = threadIdx.x & 31;
    const int n_groups = (N_NODES + RPW - 1) / RPW;      // 25000

    for (int grp = blockIdx.x * 8 + warp; grp < n_groups; grp += G1_BLOCKS * 8) {
        int row0 = grp * RPW;
        int nr = min(RPW, N_NODES - row0);

        float acc[RPW][HID];
#pragma unroll
        for (int r = 0; r < RPW; r++)
#pragma unroll
            for (int j = 0; j < HID; j++) acc[r][j] = 0.0f;

#pragma unroll
        for (int k = 0; k < 4; k++) {                    // 128 float4 / 32 lanes
            float4 xv[RPW];
#pragma unroll
            for (int r = 0; r < RPW; r++) {
                int row = row0 + (r < nr ? r : 0);       // clamp (dup work, no OOB)
                xv[r] = __ldg((const float4*)(x + (size_t)row * F_IN) + lane + 32 * k);
            }
#pragma unroll
            for (int j = 0; j < HID; j++) {
                float4 w = ((const float4*)(Wt + j * F_IN))[lane + 32 * k];
#pragma unroll
                for (int r = 0; r < RPW; r++) {
                    acc[r][j] += xv[r].x * w.x + xv[r].y * w.y
                               + xv[r].z * w.z + xv[r].w * w.w;
                }
            }
        }

        // warp tree-reduce all RPW*HID partials
#pragma unroll
        for (int r = 0; r < RPW; r++)
#pragma unroll
            for (int j = 0; j < HID; j++)
#pragma unroll
                for (int off = 16; off > 0; off >>= 1)
                    acc[r][j] += __shfl_xor_sync(0xffffffffu, acc[r][j], off);

        if (lane == 0) {
#pragma unroll
            for (int r = 0; r < RPW; r++) {
                if (r >= nr) break;
                int row = row0 + r;
                float dv = rsqrtf(g_deg[row]);
                g_dis[row] = dv;
                float4* pg = (float4*)(g_g1  + (size_t)row * HID);
                float4* pa = (float4*)(g_ac1 + (size_t)row * HID);
#pragma unroll
                for (int k = 0; k < 4; k++) {
                    float4 v = make_float4(acc[r][4*k+0]*dv, acc[r][4*k+1]*dv,
                                           acc[r][4*k+2]*dv, acc[r][4*k+3]*dv);
                    pg[k] = v;
                    pa[k] = v;
                }
            }
        }
    }
}

// ---------------------------------------------------------------------------
// K4/K6: edge propagation, 4 lanes per edge (lane q owns float4 q of the row).
// One LDG.128 + one RED.128 per thread -> ~2 L1 wavefronts per edge.
// ---------------------------------------------------------------------------
template <int LAYER>
__global__ __launch_bounds__(256) void k_edges(const int* __restrict__ ei) {
    const float* __restrict__ gsrc = (LAYER == 1 ? g_g1 : g_g2);
    float*       __restrict__ gacc = (LAYER == 1 ? g_ac1 : g_ac2);
    int t = blockIdx.x * blockDim.x + threadIdx.x;
    int e = t >> 2;
    int q = t & 3;
    if (e >= N_EDGES) return;
    int s = __ldg(&ei[e]);
    int d = __ldg(&ei[N_EDGES + e]);
    float4 v = __ldg((const float4*)(gsrc + (size_t)s * HID) + q);
    red_add_v4(gacc + (size_t)d * HID + q * 4, v);
}

// ---------------------------------------------------------------------------
// K5: finalize layer 1:  t = relu(acc1*dis + b1);  g2 = t*dis;  acc2 = g2
// ---------------------------------------------------------------------------
__global__ __launch_bounds__(256) void k_finalize1(const float* __restrict__ b1) {
    int i = blockIdx.x * blockDim.x + threadIdx.x;
    if (i >= N_NODES) return;
    float dv = g_dis[i];
    const float4* pa = (const float4*)(g_ac1 + (size_t)i * HID);
    float4* pg = (float4*)(g_g2  + (size_t)i * HID);
    float4* pc = (float4*)(g_ac2 + (size_t)i * HID);
#pragma unroll
    for (int k = 0; k < 4; k++) {
        float4 a = pa[k];
        float c0 = __ldg(&b1[4*k+0]), c1 = __ldg(&b1[4*k+1]);
        float c2 = __ldg(&b1[4*k+2]), c3 = __ldg(&b1[4*k+3]);
        float4 t;
        t.x = fmaxf(a.x * dv + c0, 0.0f) * dv;
        t.y = fmaxf(a.y * dv + c1, 0.0f) * dv;
        t.z = fmaxf(a.z * dv + c2, 0.0f) * dv;
        t.w = fmaxf(a.w * dv + c3, 0.0f) * dv;
        pg[k] = t;
        pc[k] = t;
    }
}

// ---------------------------------------------------------------------------
// K7: epilogue: p = acc2*dis; o = p @ W2 + b2; log_softmax; write out.
// ---------------------------------------------------------------------------
__global__ __launch_bounds__(256) void k_output(const float* __restrict__ W2,
                                                const float* __restrict__ b2,
                                                float* __restrict__ out) {
    __shared__ float W2s[HID * NCLS];
    __shared__ float b2s[NCLS];
    for (int idx = threadIdx.x; idx < HID * NCLS; idx += 256) W2s[idx] = W2[idx];
    for (int idx = threadIdx.x; idx < NCLS; idx += 256) b2s[idx] = b2[idx];
    __syncthreads();

    int i = blockIdx.x * blockDim.x + threadIdx.x;
    if (i >= N_NODES) return;

    float dv = g_dis[i];
    float o[NCLS];
#pragma unroll
    for (int j = 0; j < NCLS; j++) o[j] = b2s[j];

    const float4* pa = (const float4*)(g_ac2 + (size_t)i * HID);
#pragma unroll
    for (int k = 0; k < 4; k++) {
        float4 a = pa[k];
        float p0 = a.x * dv, p1 = a.y * dv, p2 = a.z * dv, p3 = a.w * dv;
        int c = 4 * k;
#pragma unroll
        for (int j = 0; j < NCLS; j++) {
            o[j] += p0 * W2s[(c+0)*NCLS + j] + p1 * W2s[(c+1)*NCLS + j]
                  + p2 * W2s[(c+2)*NCLS + j] + p3 * W2s[(c+3)*NCLS + j];
        }
    }

    float m = o[0];
#pragma unroll
    for (int j = 1; j < NCLS; j++) m = fmaxf(m, o[j]);
    float ssum = 0.0f;
#pragma unroll
    for (int j = 0; j < NCLS; j++) ssum += expf(o[j] - m);
    float ls = m + logf(ssum);

    float* op = out + (size_t)i * NCLS;
#pragma unroll
    for (int j = 0; j < NCLS; j++) op[j] = o[j] - ls;
}

// ---------------------------------------------------------------------------
extern "C" void kernel_launch(void* const* d_in, const int* in_sizes, int n_in,
                              void* d_out, int out_size) {
    (void)in_sizes; (void)n_in; (void)out_size;
    const float* x   = (const float*)d_in[0];
    const int*   ei  = (const int*)d_in[1];
    const float* W1  = (const float*)d_in[2];
    const float* b1  = (const float*)d_in[3];
    const float* W2  = (const float*)d_in[4];
    const float* b2  = (const float*)d_in[5];
    float*       out = (float*)d_out;

    const int TB = 256;
    k_init_deg  <<<(N_NODES + TB - 1) / TB, TB>>>();
    k_count_deg <<<(N_EDGES / 2 + TB - 1) / TB, TB>>>(ei);
    k_gemm1     <<<G1_BLOCKS, 256>>>(x, W1);
    k_edges<1>  <<<(N_EDGES * 4 + TB - 1) / TB, TB>>>(ei);
    k_finalize1 <<<(N_NODES + TB - 1) / TB, TB>>>(b1);
    k_edges<2>  <<<(N_EDGES * 4 + TB - 1) / TB, TB>>>(ei);
    k_output    <<<(N_NODES + TB - 1) / TB, TB>>>(W2, b2, out);
}